// round 1
// baseline (speedup 1.0000x reference)
#include <cuda_runtime.h>

#define T_STEPS 1000
#define B_TOT   256
#define FIN     39
#define H       100
#define G3      300
#define NCLS    20

typedef unsigned long long u64;

__device__ __forceinline__ u64 pk(float x, float y) {
    u64 r; asm("mov.b64 %0,{%1,%2};" : "=l"(r) : "f"(x), "f"(y)); return r;
}
__device__ __forceinline__ void fma2(u64 &d, u64 a, u64 b) {
    asm("fma.rn.f32x2 %0,%1,%2,%0;" : "+l"(d) : "l"(a), "l"(b));
}
__device__ __forceinline__ u64 add2(u64 a, u64 b) {
    u64 r; asm("add.rn.f32x2 %0,%1,%2;" : "=l"(r) : "l"(a), "l"(b)); return r;
}
__device__ __forceinline__ float hsum2(u64 a) {
    float x, y; asm("mov.b64 {%0,%1},%2;" : "=f"(x), "=f"(y) : "l"(a)); return x + y;
}
__device__ __forceinline__ void lds_v2u64(u64 &a, u64 &b, unsigned addr) {
    asm volatile("ld.shared.v2.u64 {%0,%1},[%2];" : "=l"(a), "=l"(b) : "r"(addr));
}

// sigmoid via ex2.approx (+rcp.approx): abs err ~1e-7, safe over 1000 recurrent steps
__device__ __forceinline__ float sigf(float x) {
    return __fdividef(1.0f, 1.0f + __expf(-x));
}
__device__ __forceinline__ float tanh_acc(float x) {
    return 2.0f * sigf(2.0f * x) - 1.0f;
}

__global__ void __launch_bounds__(320, 1) gru_fused_kernel(
    const float* __restrict__ mfcc0, const float* __restrict__ mfcc1,
    const float* __restrict__ mfcc2, const float* __restrict__ len0,
    const float* __restrict__ W_ih, const float* __restrict__ W_hh,
    const float* __restrict__ b_ih, const float* __restrict__ b_hh,
    const float* __restrict__ W_out, const float* __restrict__ b_out,
    float* __restrict__ out)
{
    // h packed along K as consecutive floats: h4[b] = 26 float4 (100 used + pad)
    __shared__ float4 h4[2][26];
    __shared__ float  x_sh[2][40];          // 39 used + zero pad
    __shared__ float  r_sh[2][H], z_sh[2][H], in_sh[2][H], hn_sh[2][H];
    __shared__ float  feat_sh[2][2 * H];

    const int tid = threadIdx.x;
    const int g   = tid;                    // gate index for tid < 300
    const int b0  = blockIdx.x * 2;         // global batch pair

    // zero h (incl. padding tail) and x pad
    for (int i = tid; i < 2 * 26 * 4; i += blockDim.x) ((float*)h4)[i] = 0.0f;
    if (tid < 2) x_sh[tid][39] = 0.0f;

    // ---- persistent weights in registers, packed along K ----
    u64 whh[52], wih[20];
    float big = 0.0f, bhg = 0.0f;
    if (g < G3) {
        const float* wr = W_hh + g * H;
        #pragma unroll
        for (int j = 0; j < 50; j++) whh[j] = pk(wr[2 * j], wr[2 * j + 1]);
        whh[50] = 0ull; whh[51] = 0ull;
        const float* wi = W_ih + g * FIN;
        #pragma unroll
        for (int j = 0; j < 19; j++) wih[j] = pk(wi[2 * j], wi[2 * j + 1]);
        wih[19] = pk(wi[38], 0.0f);
        big = b_ih[g]; bhg = b_hh[g];
    }

    // ---- x loader threads: tid in [100,178), one (batch, feature) each ----
    const bool loader = (tid >= 100 && tid < 100 + 2 * FIN);
    const float* xptr = nullptr;
    int lk = 0, lb = 0;
    if (loader) {
        int li = tid - 100; lb = li / FIN; lk = li % FIN;
        const float* basep = (lk < 13) ? mfcc0 : (lk < 26 ? mfcc1 : mfcc2);
        int f = (lk < 13) ? lk : (lk < 26 ? lk - 13 : lk - 26);
        xptr = basep + (size_t)(b0 + lb) * 13 + f;    // t = 0
    }
    const int XSTR = B_TOT * 13;

    // prologue: x(0) into shared
    float xr = 0.0f;
    if (loader) { xr = __ldg(xptr); xptr += XSTR; x_sh[lb][lk] = xr; }
    __syncthreads();

    float hprev[2] = {0.0f, 0.0f};
    float hs[2]    = {0.0f, 0.0f};
    float hm[2]    = {-1e30f, -1e30f};

    const unsigned hB = (unsigned)__cvta_generic_to_shared(&h4[0][0]);
    const unsigned xB = (unsigned)__cvta_generic_to_shared(&x_sh[0][0]);

    for (int t = 0; t < T_STEPS; t++) {
        // issue next-step x loads early (hidden under this step's FMAs)
        if (loader && t + 1 < T_STEPS) { xr = __ldg(xptr); xptr += XSTR; }

        float giv[2], ghv[2];
        if (g < G3) {
            #pragma unroll
            for (int b = 0; b < 2; b++) {
                u64 a0 = 0, a1 = 0, a2 = 0, a3 = 0;
                unsigned ad = hB + b * 416;
                #pragma unroll
                for (int i = 0; i < 13; i++) {
                    u64 p, q, p2, q2;
                    lds_v2u64(p,  q,  ad + i * 32);
                    lds_v2u64(p2, q2, ad + i * 32 + 16);
                    fma2(a0, whh[4 * i],     p);
                    fma2(a1, whh[4 * i + 1], q);
                    fma2(a2, whh[4 * i + 2], p2);
                    fma2(a3, whh[4 * i + 3], q2);
                }
                ghv[b] = hsum2(add2(add2(a0, a1), add2(a2, a3))) + bhg;

                u64 xa0 = 0, xa1 = 0;
                unsigned xd = xB + b * 160;
                #pragma unroll
                for (int i = 0; i < 5; i++) {
                    u64 p, q, p2, q2;
                    lds_v2u64(p,  q,  xd + i * 32);
                    lds_v2u64(p2, q2, xd + i * 32 + 16);
                    fma2(xa0, wih[4 * i],     p);
                    fma2(xa1, wih[4 * i + 1], q);
                    fma2(xa0, wih[4 * i + 2], p2);
                    fma2(xa1, wih[4 * i + 3], q2);
                }
                giv[b] = hsum2(add2(xa0, xa1)) + big;
            }
            if (g < H) {
                r_sh[0][g] = sigf(giv[0] + ghv[0]);
                r_sh[1][g] = sigf(giv[1] + ghv[1]);
            } else if (g < 2 * H) {
                z_sh[0][g - H] = sigf(giv[0] + ghv[0]);
                z_sh[1][g - H] = sigf(giv[1] + ghv[1]);
            } else {
                in_sh[0][g - 2 * H] = giv[0]; hn_sh[0][g - 2 * H] = ghv[0];
                in_sh[1][g - 2 * H] = giv[1]; hn_sh[1][g - 2 * H] = ghv[1];
            }
        }
        __syncthreads();   // (1) gates published; x_sh(t) consumed

        if (loader && t + 1 < T_STEPS) x_sh[lb][lk] = xr;

        if (g < H) {       // h-owner: combine gates, update h + pooling
            #pragma unroll
            for (int b = 0; b < 2; b++) {
                float n  = tanh_acc(in_sh[b][g] + r_sh[b][g] * hn_sh[b][g]);
                float z  = z_sh[b][g];
                float hn = n + z * (hprev[b] - n);   // (1-z)*n + z*h
                hprev[b] = hn;
                hs[b] += hn;
                hm[b] = fmaxf(hm[b], hn);
                ((float*)&h4[b][0])[g] = hn;
            }
        }
        __syncthreads();   // (2) h(t+1), x(t+1) visible
    }

    // ---- pooling features ----
    if (g < H) {
        float inv0 = 1.0f / len0[b0];
        float inv1 = 1.0f / len0[b0 + 1];
        feat_sh[0][g]     = hs[0] * inv0;
        feat_sh[0][H + g] = hm[0];
        feat_sh[1][g]     = hs[1] * inv1;
        feat_sh[1][H + g] = hm[1];
    }
    __syncthreads();

    // ---- output linear: [2 x 20] = feat[2 x 200] @ W_out^T ----
    if (tid < 2 * NCLS) {
        int bb = tid / NCLS, c = tid % NCLS;
        const float* wr = W_out + c * 2 * H;
        float acc = b_out[c];
        #pragma unroll 4
        for (int j = 0; j < 2 * H; j++) acc += feat_sh[bb][j] * wr[j];
        out[(b0 + bb) * NCLS + c] = acc;
    }
}

extern "C" void kernel_launch(void* const* d_in, const int* in_sizes, int n_in,
                              void* d_out, int out_size)
{
    const float* mfcc0 = (const float*)d_in[0];
    const float* mfcc1 = (const float*)d_in[1];
    const float* mfcc2 = (const float*)d_in[2];
    const float* len0  = (const float*)d_in[3];
    const float* W_ih  = (const float*)d_in[4];
    const float* W_hh  = (const float*)d_in[5];
    const float* b_ih  = (const float*)d_in[6];
    const float* b_hh  = (const float*)d_in[7];
    const float* W_out = (const float*)d_in[8];
    const float* b_out = (const float*)d_in[9];
    float* out = (float*)d_out;

    gru_fused_kernel<<<B_TOT / 2, 320>>>(mfcc0, mfcc1, mfcc2, len0,
                                         W_ih, W_hh, b_ih, b_hh,
                                         W_out, b_out, out);
}

// round 2
// speedup vs baseline: 1.2479x; 1.2479x over previous
#include <cuda_runtime.h>

#define T_STEPS 1000
#define B_TOT   256
#define FIN     39
#define H       100
#define G3      300
#define NCLS    20

typedef unsigned long long u64;

// 307 MB scratch for precomputed input gates gi[t][b][g] (includes b_ih)
__device__ float g_gi[(size_t)T_STEPS * B_TOT * G3];

__device__ __forceinline__ u64 pk(float x, float y) {
    u64 r; asm("mov.b64 %0,{%1,%2};" : "=l"(r) : "f"(x), "f"(y)); return r;
}
__device__ __forceinline__ void fma2(u64 &d, u64 a, u64 b) {
    asm("fma.rn.f32x2 %0,%1,%2,%0;" : "+l"(d) : "l"(a), "l"(b));
}
__device__ __forceinline__ u64 add2(u64 a, u64 b) {
    u64 r; asm("add.rn.f32x2 %0,%1,%2;" : "=l"(r) : "l"(a), "l"(b)); return r;
}
__device__ __forceinline__ float hsum2(u64 a) {
    float x, y; asm("mov.b64 {%0,%1},%2;" : "=f"(x), "=f"(y) : "l"(a)); return x + y;
}
__device__ __forceinline__ void lds_v2u64(u64 &a, u64 &b, unsigned addr) {
    asm volatile("ld.shared.v2.u64 {%0,%1},[%2];" : "=l"(a), "=l"(b) : "r"(addr));
}

// sigmoid via ex2.approx (+rcp.approx): abs err ~1e-7, safe over 1000 recurrent steps
__device__ __forceinline__ float sigf(float x) {
    return __fdividef(1.0f, 1.0f + __expf(-x));
}
__device__ __forceinline__ float tanh_acc(float x) {
    return 2.0f * sigf(2.0f * x) - 1.0f;
}

// ---------------------------------------------------------------------------
// Kernel 1: gi[t][b][g] = b_ih[g] + sum_k x[t][b][k] * W_ih[g][k]
// pairs p = t*B + b processed in tiles of 32; W_ih rows persistent in regs.
// ---------------------------------------------------------------------------
#define K1_PAIRS 256
#define K1_TILE  32

__global__ void __launch_bounds__(320) gi_precompute_kernel(
    const float* __restrict__ mfcc0, const float* __restrict__ mfcc1,
    const float* __restrict__ mfcc2,
    const float* __restrict__ W_ih, const float* __restrict__ b_ih)
{
    __shared__ __align__(16) float xt[K1_TILE][40];   // 39 feats + zero pad
    const int tid = threadIdx.x;
    const int g = (tid < G3) ? tid : (G3 - 1);

    u64 wih[20];
    {
        const float* w = W_ih + g * FIN;
        #pragma unroll
        for (int j = 0; j < 19; j++) wih[j] = pk(w[2 * j], w[2 * j + 1]);
        wih[19] = pk(w[38], 0.0f);
    }
    const float bias = b_ih[g];
    const int p0 = blockIdx.x * K1_PAIRS;

    for (int tile = 0; tile < K1_PAIRS / K1_TILE; tile++) {
        const int pb = p0 + tile * K1_TILE;
        __syncthreads();   // protect xt reuse
        for (int i = tid; i < K1_TILE * 40; i += 320) {
            int pair = i / 40, k = i - pair * 40;
            float v = 0.0f;
            if (k < 39) {
                const float* src = (k < 13) ? mfcc0 : (k < 26) ? mfcc1 : mfcc2;
                int f = (k < 13) ? k : (k < 26) ? (k - 13) : (k - 26);
                v = src[(size_t)(pb + pair) * 13 + f];
            }
            xt[pair][k] = v;
        }
        __syncthreads();

        const unsigned xB = (unsigned)__cvta_generic_to_shared(&xt[0][0]);
        #pragma unroll 4
        for (int pair = 0; pair < K1_TILE; pair++) {
            u64 a0 = 0, a1 = 0;
            unsigned ad = xB + pair * 160;
            #pragma unroll
            for (int j = 0; j < 10; j++) {
                u64 p, q; lds_v2u64(p, q, ad + j * 16);
                fma2(a0, wih[2 * j],     p);
                fma2(a1, wih[2 * j + 1], q);
            }
            if (tid < G3)
                g_gi[(size_t)(pb + pair) * G3 + g] = hsum2(add2(a0, a1)) + bias;
        }
    }
}

// ---------------------------------------------------------------------------
// Kernel 2: persistent recurrent GRU. 128 CTAs x 608 threads.
// thread = (gate g = tid>>1, K-half k2 = tid&1); lane pairs reduce via bfly(1).
// Each lane finalizes the gate for batch b = k2 only.
// h padded per half to 52 floats -> conflict-free broadcast LDS.128.
// ---------------------------------------------------------------------------
__global__ void __launch_bounds__(608, 1) gru_rec_kernel(
    const float* __restrict__ len0,
    const float* __restrict__ W_hh, const float* __restrict__ b_hh,
    const float* __restrict__ W_out, const float* __restrict__ b_out,
    float* __restrict__ out)
{
    __shared__ __align__(16) float h_sh[2][104];   // 2 halves x 52 floats, pads zero
    __shared__ float r_sh[2][H], z_sh[2][H], in_sh[2][H], hn_sh[2][H];
    __shared__ float feat_sh[2][2 * H];

    const int tid = threadIdx.x;
    const int gid = tid >> 1;
    const int g   = (gid < G3) ? gid : (G3 - 1);   // clamp threads 600..607
    const int k2  = tid & 1;                        // K-half AND batch selector
    const int b0  = blockIdx.x * 2;
    const bool act = (tid < 600);

    // zero h (incl pads)
    for (int i = tid; i < 2 * 104; i += blockDim.x) ((float*)h_sh)[i] = 0.0f;

    // persistent W_hh half-row: 50 floats = 25 u64 + 1 zero pad
    u64 whh[26];
    {
        const float* w = W_hh + g * H + k2 * 50;
        #pragma unroll
        for (int j = 0; j < 25; j++) whh[j] = pk(w[2 * j], w[2 * j + 1]);
        whh[25] = 0ull;
    }
    const float bhh = b_hh[g];

    // gi stream for OWN batch only
    const float* gp = g_gi + (size_t)(b0 + k2) * G3 + g;
    const int GSTR = B_TOT * G3;
    float gv = __ldg(gp); gp += GSTR;              // gi(t=0)

    // combine-thread state (tid < 200): hi = tid>>1, b = tid&1
    float hprev = 0.0f, hs = 0.0f, hm = -1e30f;
    const int hi_c = tid >> 1;
    const int b_c  = tid & 1;

    const unsigned hB = (unsigned)__cvta_generic_to_shared(&h_sh[0][0]) + k2 * 208;

    __syncthreads();

    for (int t = 0; t < T_STEPS; t++) {
        // prefetch gi(t+1) a full step ahead
        float gvn = 0.0f;
        if (t + 1 < T_STEPS) { gvn = __ldg(gp); gp += GSTR; }

        // half-dot for both batches (partner holds the other half)
        float red0, red1;
        {
            u64 a0 = 0, a1 = 0, c0 = 0, c1 = 0;
            #pragma unroll
            for (int j = 0; j < 13; j++) {
                u64 p, q, p2, q2;
                lds_v2u64(p,  q,  hB + j * 16);            // batch 0 half
                lds_v2u64(p2, q2, hB + 416 + j * 16);      // batch 1 half
                fma2(a0, whh[2 * j],     p);
                fma2(a1, whh[2 * j + 1], q);
                fma2(c0, whh[2 * j],     p2);
                fma2(c1, whh[2 * j + 1], q2);
            }
            red0 = hsum2(add2(a0, a1));
            red1 = hsum2(add2(c0, c1));
        }
        float o0 = __shfl_xor_sync(0xFFFFFFFFu, red0, 1);
        float o1 = __shfl_xor_sync(0xFFFFFFFFu, red1, 1);
        // full gh for OWN batch
        float gho = (k2 ? (red1 + o1) : (red0 + o0)) + bhh;

        if (act) {
            if (g < H) {
                r_sh[k2][g] = sigf(gho + gv);
            } else if (g < 2 * H) {
                z_sh[k2][g - H] = sigf(gho + gv);
            } else {
                in_sh[k2][g - 2 * H] = gv;
                hn_sh[k2][g - 2 * H] = gho;
            }
        }
        __syncthreads();   // (1) gates published

        if (tid < 200) {
            float r = r_sh[b_c][hi_c];
            float z = z_sh[b_c][hi_c];
            float n = tanh_acc(in_sh[b_c][hi_c] + r * hn_sh[b_c][hi_c]);
            float h = n + z * (hprev - n);
            hprev = h;
            hs += h;
            hm = fmaxf(hm, h);
            int slot = hi_c + (hi_c >= 50 ? 2 : 0);
            h_sh[b_c][slot] = h;
        }
        gv = gvn;
        __syncthreads();   // (2) h(t+1) visible
    }

    // pooling features
    if (tid < 200) {
        float inv = 1.0f / len0[b0 + b_c];
        feat_sh[b_c][hi_c]     = hs * inv;
        feat_sh[b_c][H + hi_c] = hm;
    }
    __syncthreads();

    // output linear: [2 x 20] = feat[2 x 200] @ W_out^T + b_out
    if (tid < 2 * NCLS) {
        int bb = tid / NCLS, c = tid % NCLS;
        const float* wr = W_out + c * 2 * H;
        float acc = b_out[c];
        #pragma unroll 4
        for (int j = 0; j < 2 * H; j++) acc += feat_sh[bb][j] * wr[j];
        out[(b0 + bb) * NCLS + c] = acc;
    }
}

extern "C" void kernel_launch(void* const* d_in, const int* in_sizes, int n_in,
                              void* d_out, int out_size)
{
    const float* mfcc0 = (const float*)d_in[0];
    const float* mfcc1 = (const float*)d_in[1];
    const float* mfcc2 = (const float*)d_in[2];
    const float* len0  = (const float*)d_in[3];
    const float* W_ih  = (const float*)d_in[4];
    const float* W_hh  = (const float*)d_in[5];
    const float* b_ih  = (const float*)d_in[6];
    const float* b_hh  = (const float*)d_in[7];
    const float* W_out = (const float*)d_in[8];
    const float* b_out = (const float*)d_in[9];
    float* out = (float*)d_out;

    gi_precompute_kernel<<<(T_STEPS * B_TOT) / K1_PAIRS, 320>>>(
        mfcc0, mfcc1, mfcc2, W_ih, b_ih);
    gru_rec_kernel<<<B_TOT / 2, 608>>>(len0, W_hh, b_hh, W_out, b_out, out);
}

// round 3
// speedup vs baseline: 1.3125x; 1.0518x over previous
#include <cuda_runtime.h>

#define T_STEPS 1000
#define B_TOT   256
#define FIN     39
#define H       100
#define G3      300
#define NCLS    20
#define GSTR    (B_TOT * G3)

typedef unsigned long long u64;

// 307 MB scratch for precomputed input gates gi[t][b][g] (includes b_ih)
__device__ float g_gi[(size_t)T_STEPS * B_TOT * G3];

__device__ __forceinline__ u64 pk(float x, float y) {
    u64 r; asm("mov.b64 %0,{%1,%2};" : "=l"(r) : "f"(x), "f"(y)); return r;
}
__device__ __forceinline__ void fma2(u64 &d, u64 a, u64 b) {
    asm("fma.rn.f32x2 %0,%1,%2,%0;" : "+l"(d) : "l"(a), "l"(b));
}
__device__ __forceinline__ u64 add2(u64 a, u64 b) {
    u64 r; asm("add.rn.f32x2 %0,%1,%2;" : "=l"(r) : "l"(a), "l"(b)); return r;
}
__device__ __forceinline__ float hsum2(u64 a) {
    float x, y; asm("mov.b64 {%0,%1},%2;" : "=f"(x), "=f"(y) : "l"(a)); return x + y;
}
__device__ __forceinline__ void lds_v2u64(u64 &a, u64 &b, unsigned addr) {
    asm volatile("ld.shared.v2.u64 {%0,%1},[%2];" : "=l"(a), "=l"(b) : "r"(addr));
}
__device__ __forceinline__ float sigf(float x) {
    return __fdividef(1.0f, 1.0f + __expf(-x));
}
__device__ __forceinline__ float tanh_acc(float x) {
    return 2.0f * sigf(2.0f * x) - 1.0f;
}

// ---------------------------------------------------------------------------
// Kernel 1: gi[t][b][g] = b_ih[g] + sum_k x[t][b][k] * W_ih[g][k]
// 64 pairs per CTA, 2 tiles of 32, double-buffered x, 2-pair ILP.
// ---------------------------------------------------------------------------
#define K1_PAIRS 64
#define K1_TILE  32

__global__ void __launch_bounds__(320, 2) gi_precompute_kernel(
    const float* __restrict__ mfcc0, const float* __restrict__ mfcc1,
    const float* __restrict__ mfcc2,
    const float* __restrict__ W_ih, const float* __restrict__ b_ih)
{
    __shared__ __align__(16) float xt[2][K1_TILE][40];
    const int tid = threadIdx.x;
    const int g = (tid < G3) ? tid : (G3 - 1);

    u64 wih[20];
    {
        const float* w = W_ih + g * FIN;
        #pragma unroll
        for (int j = 0; j < 19; j++) wih[j] = pk(w[2 * j], w[2 * j + 1]);
        wih[19] = pk(w[38], 0.0f);
    }
    const float bias = b_ih[g];
    const int p0 = blockIdx.x * K1_PAIRS;

    // fill assignment: each thread owns 4 slots of the 1280-float tile
    int fpair[4], fk[4];
    const float* fptr[4];
    bool fok[4];
    #pragma unroll
    for (int s = 0; s < 4; s++) {
        int idx = tid + s * 320;
        int pr = idx / 40, k = idx - pr * 40;
        fpair[s] = pr; fk[s] = k;
        fok[s] = (k < 39);
        const float* src = (k < 13) ? mfcc0 : (k < 26) ? mfcc1 : mfcc2;
        int f = (k < 13) ? k : (k < 26) ? (k - 13) : (k - 26);
        fptr[s] = src + (size_t)(p0 + pr) * 13 + f;
    }

    // prologue: tile 0
    #pragma unroll
    for (int s = 0; s < 4; s++)
        xt[0][fpair[s]][fk[s]] = fok[s] ? __ldg(fptr[s]) : 0.0f;
    __syncthreads();

    const unsigned xB0 = (unsigned)__cvta_generic_to_shared(&xt[0][0][0]);

    for (int tile = 0; tile < K1_PAIRS / K1_TILE; tile++) {
        // issue loads for next tile into the other buffer
        if (tile + 1 < K1_PAIRS / K1_TILE) {
            #pragma unroll
            for (int s = 0; s < 4; s++) {
                fptr[s] += K1_TILE * 13;
                xt[(tile + 1) & 1][fpair[s]][fk[s]] = fok[s] ? __ldg(fptr[s]) : 0.0f;
            }
        }
        const unsigned xB = xB0 + (tile & 1) * (K1_TILE * 40 * 4);
        const int pb = p0 + tile * K1_TILE;
        #pragma unroll 2
        for (int pair = 0; pair < K1_TILE; pair += 2) {
            u64 a0 = 0, a1 = 0, c0 = 0, c1 = 0;
            unsigned ad = xB + pair * 160;
            #pragma unroll
            for (int j = 0; j < 10; j++) {
                u64 p, q, p2, q2;
                lds_v2u64(p,  q,  ad + j * 16);
                lds_v2u64(p2, q2, ad + 160 + j * 16);
                fma2(a0, wih[2 * j],     p);
                fma2(a1, wih[2 * j + 1], q);
                fma2(c0, wih[2 * j],     p2);
                fma2(c1, wih[2 * j + 1], q2);
            }
            if (tid < G3) {
                g_gi[(size_t)(pb + pair) * G3 + g]     = hsum2(add2(a0, a1)) + bias;
                g_gi[(size_t)(pb + pair + 1) * G3 + g] = hsum2(add2(c0, c1)) + bias;
            }
        }
        __syncthreads();
    }
}

// ---------------------------------------------------------------------------
// Kernel 2: persistent recurrent GRU. 128 CTAs x 400 threads.
// thread = (h = tid>>2, chunk c = tid&3). Each thread computes r,z,n gate
// partials for its h over K-chunk [c*28, c*28+28) (zero-padded), both batches.
// Quad bfly-reduction; lane c<2 finalizes batch b=c fully in registers.
// h double-buffered in smem -> ONE barrier per step.
// ---------------------------------------------------------------------------
#define CH  28          // chunk floats (112B, 16B-aligned)
#define HP  112         // padded h per batch

__global__ void __launch_bounds__(400, 1) gru_rec_kernel(
    const float* __restrict__ len0,
    const float* __restrict__ W_hh, const float* __restrict__ b_hh,
    const float* __restrict__ W_out, const float* __restrict__ b_out,
    float* __restrict__ out)
{
    __shared__ __align__(16) float h_sh[2][2][HP];   // [buf][batch][v], pads zero
    __shared__ float feat_sh[2][2 * H];

    const int tid = threadIdx.x;
    const int h   = tid >> 2;          // 0..99
    const int c   = tid & 3;           // K-chunk, and batch selector for c<2
    const int b0  = blockIdx.x * 2;
    const unsigned smask = (tid < 384) ? 0xFFFFFFFFu : 0x0000FFFFu;

    // zero both h buffers (incl pads)
    for (int i = tid; i < 2 * 2 * HP; i += blockDim.x) ((float*)h_sh)[i] = 0.0f;

    // persistent W_hh chunk rows for 3 gates (r,z,n), zero-padded
    const int k0   = c * CH;
    const int kcnt = (k0 + CH <= H) ? CH : (H - k0);   // 28 or 16
    u64 w[3][CH / 2];
    #pragma unroll
    for (int i = 0; i < 3; i++) {
        const float* wr = W_hh + (h + i * H) * H + k0;
        #pragma unroll
        for (int j = 0; j < CH / 2; j++) {
            float x0 = (2 * j     < kcnt) ? wr[2 * j]     : 0.0f;
            float x1 = (2 * j + 1 < kcnt) ? wr[2 * j + 1] : 0.0f;
            w[i][j] = pk(x0, x1);
        }
    }

    // finalize-lane state (c < 2, batch b = c)
    const bool fin = (c < 2);
    float bh0 = 0.0f, bh1 = 0.0f, bh2 = 0.0f;
    const float* gp = g_gi;
    if (fin) {
        bh0 = b_hh[h]; bh1 = b_hh[h + H]; bh2 = b_hh[h + 2 * H];
        gp = g_gi + (size_t)(b0 + c) * G3 + h;
    }
    float hprev = 0.0f, hs = 0.0f, hm = -1e30f;

    // prefetch gi(t=0)
    float gv0 = 0.0f, gv1 = 0.0f, gv2 = 0.0f;
    if (fin) { gv0 = __ldg(gp); gv1 = __ldg(gp + H); gv2 = __ldg(gp + 2 * H); }

    const unsigned hB = (unsigned)__cvta_generic_to_shared(&h_sh[0][0][0]) + c * (CH * 4);
    int p = 0;
    __syncthreads();

    for (int t = 0; t < T_STEPS; t++) {
        // prefetch gi(t+1) ~1.5 steps before use
        float gn0 = 0.0f, gn1 = 0.0f, gn2 = 0.0f;
        if (fin && t + 1 < T_STEPS) {
            const float* gq = gp + (size_t)(t + 1) * GSTR;
            gn0 = __ldg(gq); gn1 = __ldg(gq + H); gn2 = __ldg(gq + 2 * H);
        }

        // partial dots: 3 gates x 2 batches, 2 accumulators each
        u64 a00 = 0, a01 = 0, a10 = 0, a11 = 0, a20 = 0, a21 = 0;   // batch 0
        u64 d00 = 0, d01 = 0, d10 = 0, d11 = 0, d20 = 0, d21 = 0;   // batch 1
        {
            const unsigned ad = hB + p * (2 * HP * 4);
            #pragma unroll
            for (int j = 0; j < CH / 4; j++) {           // 7 iters, 16B each
                u64 q0, q1, r0, r1;
                lds_v2u64(q0, q1, ad + j * 16);                  // batch 0
                lds_v2u64(r0, r1, ad + HP * 4 + j * 16);         // batch 1
                fma2(a00, w[0][2 * j], q0); fma2(a01, w[0][2 * j + 1], q1);
                fma2(a10, w[1][2 * j], q0); fma2(a11, w[1][2 * j + 1], q1);
                fma2(a20, w[2][2 * j], q0); fma2(a21, w[2][2 * j + 1], q1);
                fma2(d00, w[0][2 * j], r0); fma2(d01, w[0][2 * j + 1], r1);
                fma2(d10, w[1][2 * j], r0); fma2(d11, w[1][2 * j + 1], r1);
                fma2(d20, w[2][2 * j], r0); fma2(d21, w[2][2 * j + 1], r1);
            }
        }
        float s0b0 = hsum2(add2(a00, a01));
        float s1b0 = hsum2(add2(a10, a11));
        float s2b0 = hsum2(add2(a20, a21));
        float s0b1 = hsum2(add2(d00, d01));
        float s1b1 = hsum2(add2(d10, d11));
        float s2b1 = hsum2(add2(d20, d21));

        // quad reduction over chunks
        s0b0 += __shfl_xor_sync(smask, s0b0, 1); s0b0 += __shfl_xor_sync(smask, s0b0, 2);
        s1b0 += __shfl_xor_sync(smask, s1b0, 1); s1b0 += __shfl_xor_sync(smask, s1b0, 2);
        s2b0 += __shfl_xor_sync(smask, s2b0, 1); s2b0 += __shfl_xor_sync(smask, s2b0, 2);
        s0b1 += __shfl_xor_sync(smask, s0b1, 1); s0b1 += __shfl_xor_sync(smask, s0b1, 2);
        s1b1 += __shfl_xor_sync(smask, s1b1, 1); s1b1 += __shfl_xor_sync(smask, s1b1, 2);
        s2b1 += __shfl_xor_sync(smask, s2b1, 1); s2b1 += __shfl_xor_sync(smask, s2b1, 2);

        if (fin) {
            float hr = (c == 0) ? s0b0 : s0b1;
            float hz = (c == 0) ? s1b0 : s1b1;
            float hn = (c == 0) ? s2b0 : s2b1;
            float r = sigf(gv0 + hr + bh0);
            float z = sigf(gv1 + hz + bh1);
            float n = tanh_acc(gv2 + r * (hn + bh2));
            float hnew = n + z * (hprev - n);
            hprev = hnew;
            hs += hnew;
            hm = fmaxf(hm, hnew);
            h_sh[1 - p][c][h] = hnew;
        }
        gv0 = gn0; gv1 = gn1; gv2 = gn2;
        __syncthreads();
        p ^= 1;
    }

    // pooling features
    if (fin) {
        float inv = 1.0f / len0[b0 + c];
        feat_sh[c][h]     = hs * inv;
        feat_sh[c][H + h] = hm;
    }
    __syncthreads();

    // output linear: [2 x 20] = feat[2 x 200] @ W_out^T + b_out
    if (tid < 2 * NCLS) {
        int bb = tid / NCLS, cc = tid % NCLS;
        const float* wr = W_out + cc * 2 * H;
        float acc = b_out[cc];
        #pragma unroll 4
        for (int j = 0; j < 2 * H; j++) acc += feat_sh[bb][j] * wr[j];
        out[(b0 + bb) * NCLS + cc] = acc;
    }
}

extern "C" void kernel_launch(void* const* d_in, const int* in_sizes, int n_in,
                              void* d_out, int out_size)
{
    const float* mfcc0 = (const float*)d_in[0];
    const float* mfcc1 = (const float*)d_in[1];
    const float* mfcc2 = (const float*)d_in[2];
    const float* len0  = (const float*)d_in[3];
    const float* W_ih  = (const float*)d_in[4];
    const float* W_hh  = (const float*)d_in[5];
    const float* b_ih  = (const float*)d_in[6];
    const float* b_hh  = (const float*)d_in[7];
    const float* W_out = (const float*)d_in[8];
    const float* b_out = (const float*)d_in[9];
    float* out = (float*)d_out;

    gi_precompute_kernel<<<(T_STEPS * B_TOT) / K1_PAIRS, 320>>>(
        mfcc0, mfcc1, mfcc2, W_ih, b_ih);
    gru_rec_kernel<<<B_TOT / 2, 400>>>(len0, W_hh, b_hh, W_out, b_out, out);
}